// round 5
// baseline (speedup 1.0000x reference)
#include <cuda_runtime.h>
#include <cstdint>

#define MAXN 50000
#define MAXE 1600000

// ---------------- device scratch (no allocations allowed) ----------------
__device__ __align__(16) float g_h1 [MAXN * 128];  // layer1 features  [N,H=8,C=16]
__device__ __align__(16) float g_h1e[MAXN * 128];  // layer1 output after agg+bias+ELU
__device__ __align__(16) float g_sA1[MAXN * 8];    // dot(h1, att_src1) -> used at dst
__device__ __align__(16) float g_sB1[MAXN * 8];    // dot(h1, att_dst1) -> used at src
__device__ __align__(16) float g_h2 [MAXN * 16];   // layer2 features [N,16]
__device__ float g_sA2[MAXN];
__device__ float g_sB2[MAXN];
// CSR by destination (self loops included)
__device__ int g_deg[MAXN];
__device__ int g_rp [MAXN + 1];
__device__ int g_cur[MAXN];
__device__ int g_csr[MAXE + MAXN];

__device__ __forceinline__ float lrelu(float x) { return x > 0.f ? x : 0.2f * x; }

// ------------------------- CSR build --------------------------------------
__global__ void k_deginit(int n) {
    int i = blockIdx.x * blockDim.x + threadIdx.x;
    if (i < n) g_deg[i] = 1;                 // self loop pre-counted
}

__global__ void k_hist(const int* __restrict__ ei, int e) {
    int t = blockIdx.x * blockDim.x + threadIdx.x;
    if (t < e) atomicAdd(&g_deg[ei[e + t]], 1);
}

// single-block exclusive scan of g_deg -> g_rp (and g_cur copy)
__global__ void k_scan(int n) {
    __shared__ int ssum[1024];
    int tid = threadIdx.x;
    int chunk = (n + 1023) >> 10;
    int start = tid * chunk;
    int stop  = min(start + chunk, n);
    int sum = 0;
    for (int i = start; i < stop; i++) sum += g_deg[i];
    ssum[tid] = sum;
    __syncthreads();
    for (int off = 1; off < 1024; off <<= 1) {
        int t = (tid >= off) ? ssum[tid - off] : 0;
        __syncthreads();
        ssum[tid] += t;
        __syncthreads();
    }
    int run = ssum[tid] - sum;               // exclusive prefix
    for (int i = start; i < stop; i++) {
        int d = g_deg[i];
        g_rp[i]  = run;
        g_cur[i] = run;
        run += d;
    }
    if (tid == 1023) g_rp[n] = ssum[1023];
}

__global__ void k_scatter(const int* __restrict__ ei, int e, int n) {
    int t = blockIdx.x * blockDim.x + threadIdx.x;
    int ep = e + n;
    if (t >= ep) return;
    int s, d;
    if (t < e) { s = ei[t]; d = ei[e + t]; } else { s = d = t - e; }
    int pos = atomicAdd(&g_cur[d], 1);
    g_csr[pos] = s;
}

// ------------------- GEMM1: h1 = x @ W1^T  (N,128)x(128,128) --------------
// 128 threads (one per output channel), 16 nodes (8 node-pairs) per block.
// Accumulators are packed f32x2 node-pairs driven by fma.rn.f32x2 (FFMA2):
// halves FMA-pipe work vs scalar FFMA. Smem tile is pair-interleaved so one
// LDS.128 yields two ready-packed 64-bit b-operands (no repack movs).
__global__ void k_gemm1(const float* __restrict__ x, const float* __restrict__ W, int n) {
    __shared__ float4 xsp[8][64];   // [pair][kk]=(x0[2k],x1[2k],x0[2k+1],x1[2k+1])
    int o  = threadIdx.x;
    int n0 = blockIdx.x * 16;
    const float2* xv = (const float2*)x;     // row stride 64 float2
#pragma unroll
    for (int r = 0; r < 4; r++) {
        int idx = r * 128 + o;               // 0..511
        int p = idx >> 6, kk = idx & 63;
        int na = n0 + 2 * p, nb = na + 1;
        float2 a = (na < n) ? xv[na * 64 + kk] : make_float2(0.f, 0.f);
        float2 b = (nb < n) ? xv[nb * 64 + kk] : make_float2(0.f, 0.f);
        xsp[p][kk] = make_float4(a.x, b.x, a.y, b.y);
    }
    __syncthreads();
    unsigned long long acc[8];
#pragma unroll
    for (int p = 0; p < 8; p++) acc[p] = 0ull;
    const float2* Wv = (const float2*)W;
#pragma unroll 4
    for (int kk = 0; kk < 64; kk++) {
        float2 w = __ldg(&Wv[o * 64 + kk]);
        unsigned long long wx, wy;
        unsigned wxu = __float_as_uint(w.x), wyu = __float_as_uint(w.y);
        asm("mov.b64 %0, {%1,%1};" : "=l"(wx) : "r"(wxu));
        asm("mov.b64 %0, {%1,%1};" : "=l"(wy) : "r"(wyu));
#pragma unroll
        for (int p = 0; p < 8; p++) {
            ulonglong2 q = *reinterpret_cast<const ulonglong2*>(&xsp[p][kk]);
            asm("fma.rn.f32x2 %0, %1, %2, %0;" : "+l"(acc[p]) : "l"(wx), "l"(q.x));
            asm("fma.rn.f32x2 %0, %1, %2, %0;" : "+l"(acc[p]) : "l"(wy), "l"(q.y));
        }
    }
#pragma unroll
    for (int p = 0; p < 8; p++) {
        unsigned lo, hi;
        asm("mov.b64 {%0,%1}, %2;" : "=r"(lo), "=r"(hi) : "l"(acc[p]));
        int na = n0 + 2 * p;
        if (na < n)     g_h1[na * 128 + o]       = __uint_as_float(lo);
        if (na + 1 < n) g_h1[(na + 1) * 128 + o] = __uint_as_float(hi);
    }
}

// --------- per-node attention scalars, layer 1 (thread per (n,h)) ---------
__global__ void k_att1(const float* __restrict__ att_src, const float* __restrict__ att_dst, int n) {
    int t = blockIdx.x * blockDim.x + threadIdx.x;
    if (t >= n * 8) return;
    int nd = t >> 3, h = t & 7;
    const float4* hv = (const float4*)g_h1 + nd * 32 + h * 4;
    const float4* as = (const float4*)att_src + h * 4;
    const float4* ad = (const float4*)att_dst + h * 4;
    float sa = 0.f, sb = 0.f;
#pragma unroll
    for (int j = 0; j < 4; j++) {
        float4 hq = hv[j], aq = as[j], dq = ad[j];
        sa += hq.x*aq.x + hq.y*aq.y + hq.z*aq.z + hq.w*aq.w;
        sb += hq.x*dq.x + hq.y*dq.y + hq.z*dq.z + hq.w*dq.w;
    }
    g_sA1[t] = sa;   // pairs with dst
    g_sB1[t] = sb;   // pairs with src
}

// ------ layer1 fused gather: softmax-weighted agg + bias + ELU ------------
// one warp per dst node; lane = (head h = lane>>2, 4 channels = float4)
// 4-way edge unroll: 4 independent load chains per iteration (MLP 4x).
__global__ void k_gather1(const float* __restrict__ b1, int n) {
    int w = (blockIdx.x * blockDim.x + threadIdx.x) >> 5;
    if (w >= n) return;
    int lane = threadIdx.x & 31;
    int h = lane >> 2;
    int i   = g_rp[w];
    int end = g_rp[w + 1];
    float sAd = g_sA1[w * 8 + h];
    const float4* h1v = (const float4*)g_h1;
    float4 acc0 = make_float4(0.f,0.f,0.f,0.f);
    float4 acc1 = make_float4(0.f,0.f,0.f,0.f);
    float d0 = 0.f, d1 = 0.f;
    for (; i + 4 <= end; i += 4) {
        int s0 = __ldg(&g_csr[i + 0]);
        int s1 = __ldg(&g_csr[i + 1]);
        int s2 = __ldg(&g_csr[i + 2]);
        int s3 = __ldg(&g_csr[i + 3]);
        float a0 = g_sB1[s0 * 8 + h];
        float a1 = g_sB1[s1 * 8 + h];
        float a2 = g_sB1[s2 * 8 + h];
        float a3 = g_sB1[s3 * 8 + h];
        float4 f0 = h1v[s0 * 32 + lane];
        float4 f1 = h1v[s1 * 32 + lane];
        float4 f2 = h1v[s2 * 32 + lane];
        float4 f3 = h1v[s3 * 32 + lane];
        float e0 = __expf(lrelu(sAd + a0));
        float e1 = __expf(lrelu(sAd + a1));
        float e2 = __expf(lrelu(sAd + a2));
        float e3 = __expf(lrelu(sAd + a3));
        acc0.x = fmaf(e0,f0.x,acc0.x); acc0.y = fmaf(e0,f0.y,acc0.y);
        acc0.z = fmaf(e0,f0.z,acc0.z); acc0.w = fmaf(e0,f0.w,acc0.w);
        acc1.x = fmaf(e1,f1.x,acc1.x); acc1.y = fmaf(e1,f1.y,acc1.y);
        acc1.z = fmaf(e1,f1.z,acc1.z); acc1.w = fmaf(e1,f1.w,acc1.w);
        acc0.x = fmaf(e2,f2.x,acc0.x); acc0.y = fmaf(e2,f2.y,acc0.y);
        acc0.z = fmaf(e2,f2.z,acc0.z); acc0.w = fmaf(e2,f2.w,acc0.w);
        acc1.x = fmaf(e3,f3.x,acc1.x); acc1.y = fmaf(e3,f3.y,acc1.y);
        acc1.z = fmaf(e3,f3.z,acc1.z); acc1.w = fmaf(e3,f3.w,acc1.w);
        d0 += e0 + e2; d1 += e1 + e3;
    }
    for (; i < end; i++) {
        int s = __ldg(&g_csr[i]);
        float e0 = __expf(lrelu(sAd + g_sB1[s * 8 + h]));
        float4 f0 = h1v[s * 32 + lane];
        acc0.x = fmaf(e0,f0.x,acc0.x); acc0.y = fmaf(e0,f0.y,acc0.y);
        acc0.z = fmaf(e0,f0.z,acc0.z); acc0.w = fmaf(e0,f0.w,acc0.w);
        d0 += e0;
    }
    float inv = 1.f / (d0 + d1);
    float4 b = ((const float4*)b1)[lane];
    float4 v;
    v.x = (acc0.x + acc1.x) * inv + b.x;
    v.y = (acc0.y + acc1.y) * inv + b.y;
    v.z = (acc0.z + acc1.z) * inv + b.z;
    v.w = (acc0.w + acc1.w) * inv + b.w;
    v.x = v.x > 0.f ? v.x : (__expf(v.x) - 1.f);
    v.y = v.y > 0.f ? v.y : (__expf(v.y) - 1.f);
    v.z = v.z > 0.f ? v.z : (__expf(v.z) - 1.f);
    v.w = v.w > 0.f ? v.w : (__expf(v.w) - 1.f);
    ((float4*)g_h1e)[w * 32 + lane] = v;
}

// ------------------- GEMM2: h2 = h1e @ W2^T  (N,128)x(128,16) -------------
__global__ void k_gemm2(const float* __restrict__ W2, int n) {
    __shared__ float4 xs[8][32];
    int tid = threadIdx.x;                   // 128 threads
    int n0 = blockIdx.x * 8;
    const float4* hv = (const float4*)g_h1e;
#pragma unroll
    for (int r = 0; r < 2; r++) {
        int idx = r * 128 + tid;
        int i = idx >> 5, k4 = idx & 31;
        int node = n0 + i;
        xs[i][k4] = (node < n) ? hv[node * 32 + k4] : make_float4(0.f, 0.f, 0.f, 0.f);
    }
    __syncthreads();
    int o = tid & 15, i = tid >> 4;
    const float4* Wv = (const float4*)W2;
    float acc = 0.f;
#pragma unroll 4
    for (int k4 = 0; k4 < 32; k4++) {
        float4 w = __ldg(&Wv[o * 32 + k4]);
        float4 xq = xs[i][k4];
        acc = fmaf(w.x, xq.x, fmaf(w.y, xq.y, fmaf(w.z, xq.z, fmaf(w.w, xq.w, acc))));
    }
    int node = n0 + i;
    if (node < n) g_h2[node * 16 + o] = acc;
}

// ------------- per-node attention scalars, layer 2 ------------------------
__global__ void k_att2(const float* __restrict__ att_src, const float* __restrict__ att_dst, int n) {
    int t = blockIdx.x * blockDim.x + threadIdx.x;
    if (t >= n) return;
    const float4* hv = (const float4*)g_h2 + t * 4;
    const float4* as = (const float4*)att_src;
    const float4* ad = (const float4*)att_dst;
    float sa = 0.f, sb = 0.f;
#pragma unroll
    for (int j = 0; j < 4; j++) {
        float4 hq = hv[j], aq = as[j], dq = ad[j];
        sa += hq.x*aq.x + hq.y*aq.y + hq.z*aq.z + hq.w*aq.w;
        sb += hq.x*dq.x + hq.y*dq.y + hq.z*dq.z + hq.w*dq.w;
    }
    g_sA2[t] = sa;
    g_sB2[t] = sb;
}

// ---- layer2 fused gather: softmax agg + bias + log_softmax ---------------
// 16-lane group per dst node (2 dsts per warp); lane = channel; 2-way unroll
__global__ void k_gather2(const float* __restrict__ b2, float* __restrict__ out, int n) {
    int gid = blockIdx.x * blockDim.x + threadIdx.x;
    int g0 = gid >> 4;
    int g = (g0 < n) ? g0 : (n - 1);         // clamp; keep full warp alive for shfl
    int c = gid & 15;
    int i   = g_rp[g];
    int end = g_rp[g + 1];
    float sAd = g_sA2[g];
    float a0 = 0.f, a1 = 0.f, d0 = 0.f, d1 = 0.f;
    for (; i + 2 <= end; i += 2) {
        int s0 = __ldg(&g_csr[i]);
        int s1 = __ldg(&g_csr[i + 1]);
        float b0v = g_sB2[s0], b1v = g_sB2[s1];
        float f0 = g_h2[s0 * 16 + c], f1 = g_h2[s1 * 16 + c];
        float e0 = __expf(lrelu(sAd + b0v));
        float e1 = __expf(lrelu(sAd + b1v));
        a0 = fmaf(e0, f0, a0); d0 += e0;
        a1 = fmaf(e1, f1, a1); d1 += e1;
    }
    if (i < end) {
        int s = __ldg(&g_csr[i]);
        float e0 = __expf(lrelu(sAd + g_sB2[s]));
        a0 = fmaf(e0, g_h2[s * 16 + c], a0); d0 += e0;
    }
    float v = (a0 + a1) / (d0 + d1) + b2[c];
    // log-softmax across the 16 lanes of this dst
    float m = v;
#pragma unroll
    for (int o = 8; o; o >>= 1) m = fmaxf(m, __shfl_xor_sync(0xffffffffu, m, o, 16));
    float ssum = __expf(v - m);
#pragma unroll
    for (int o = 8; o; o >>= 1) ssum += __shfl_xor_sync(0xffffffffu, ssum, o, 16);
    if (g0 < n) out[g0 * 16 + c] = v - m - logf(ssum);
}

// ---------------------------------------------------------------------------
extern "C" void kernel_launch(void* const* d_in, const int* in_sizes, int n_in,
                              void* d_out, int out_size) {
    const float* x   = (const float*)d_in[0];
    const int*   ei  = (const int*)  d_in[1];
    const float* W1  = (const float*)d_in[2];
    const float* as1 = (const float*)d_in[3];
    const float* ad1 = (const float*)d_in[4];
    const float* b1  = (const float*)d_in[5];
    const float* W2  = (const float*)d_in[6];
    const float* as2 = (const float*)d_in[7];
    const float* ad2 = (const float*)d_in[8];
    const float* b2  = (const float*)d_in[9];
    float* out = (float*)d_out;

    int n  = in_sizes[0] / 128;   // 50000 nodes
    int e  = in_sizes[1] / 2;     // 1.6M edges (before self loops)
    int ep = e + n;

    const int BS = 256;
    // CSR build (reused by both layers)
    k_deginit<<<(n + BS - 1) / BS, BS>>>(n);
    k_hist   <<<(e + BS - 1) / BS, BS>>>(ei, e);
    k_scan   <<<1, 1024>>>(n);
    k_scatter<<<(ep + BS - 1) / BS, BS>>>(ei, e, n);
    // layer 1
    k_gemm1  <<<(n + 15) / 16, 128>>>(x, W1, n);
    k_att1   <<<(n * 8 + BS - 1) / BS, BS>>>(as1, ad1, n);
    k_gather1<<<(n * 32 + BS - 1) / BS, BS>>>(b1, n);
    // layer 2
    k_gemm2  <<<(n + 7) / 8, 128>>>(W2, n);
    k_att2   <<<(n + BS - 1) / BS, BS>>>(as2, ad2, n);
    k_gather2<<<(n * 16 + BS - 1) / BS, BS>>>(b2, out, n);
}

// round 6
// speedup vs baseline: 1.0001x; 1.0001x over previous
#include <cuda_runtime.h>
#include <cstdint>

#define MAXN 50000
#define MAXE 1600000

// ---------------- device scratch (no allocations allowed) ----------------
__device__ __align__(16) float g_h1 [MAXN * 128];  // layer1 features  [N,H=8,C=16]
__device__ __align__(16) float g_h1e[MAXN * 128];  // layer1 output after agg+bias+ELU
__device__ __align__(16) float g_sA1[MAXN * 8];    // dot(h1, att_src1) -> used at dst
__device__ __align__(16) float g_sB1[MAXN * 8];    // dot(h1, att_dst1) -> used at src
__device__ __align__(16) float g_h2 [MAXN * 16];   // layer2 features [N,16]
__device__ float g_sA2[MAXN];
__device__ float g_sB2[MAXN];
// CSR by destination (self loops included)
__device__ int g_deg[MAXN];
__device__ int g_rp [MAXN + 1];
__device__ int g_cur[MAXN];
__device__ int g_csr[MAXE + MAXN];

__device__ __forceinline__ float lrelu(float x) { return x > 0.f ? x : 0.2f * x; }

// ------------------------- CSR build --------------------------------------
__global__ void k_deginit(int n) {
    int i = blockIdx.x * blockDim.x + threadIdx.x;
    if (i < n) g_deg[i] = 1;                 // self loop pre-counted
}

__global__ void k_hist(const int* __restrict__ ei, int e) {
    int t = blockIdx.x * blockDim.x + threadIdx.x;
    if (t < e) atomicAdd(&g_deg[ei[e + t]], 1);
}

// single-block exclusive scan of g_deg -> g_rp (and g_cur copy)
__global__ void k_scan(int n) {
    __shared__ int ssum[1024];
    int tid = threadIdx.x;
    int chunk = (n + 1023) >> 10;
    int start = tid * chunk;
    int stop  = min(start + chunk, n);
    int sum = 0;
    for (int i = start; i < stop; i++) sum += g_deg[i];
    ssum[tid] = sum;
    __syncthreads();
    for (int off = 1; off < 1024; off <<= 1) {
        int t = (tid >= off) ? ssum[tid - off] : 0;
        __syncthreads();
        ssum[tid] += t;
        __syncthreads();
    }
    int run = ssum[tid] - sum;               // exclusive prefix
    for (int i = start; i < stop; i++) {
        int d = g_deg[i];
        g_rp[i]  = run;
        g_cur[i] = run;
        run += d;
    }
    if (tid == 1023) g_rp[n] = ssum[1023];
}

__global__ void k_scatter(const int* __restrict__ ei, int e, int n) {
    int t = blockIdx.x * blockDim.x + threadIdx.x;
    int ep = e + n;
    if (t >= ep) return;
    int s, d;
    if (t < e) { s = ei[t]; d = ei[e + t]; } else { s = d = t - e; }
    int pos = atomicAdd(&g_cur[d], 1);
    g_csr[pos] = s;
}

// ------------------- GEMM1: h1 = x @ W1^T  (N,128)x(128,128) --------------
// 128 threads (one per output channel), 16 nodes (8 node-pairs) per block.
// Accumulators are packed f32x2 node-pairs driven by fma.rn.f32x2 (FFMA2):
// halves FMA-pipe work vs scalar FFMA. Smem tile is pair-interleaved so one
// LDS.128 yields two ready-packed 64-bit b-operands (no repack movs).
__global__ void k_gemm1(const float* __restrict__ x, const float* __restrict__ W, int n) {
    __shared__ float4 xsp[8][64];   // [pair][kk]=(x0[2k],x1[2k],x0[2k+1],x1[2k+1])
    int o  = threadIdx.x;
    int n0 = blockIdx.x * 16;
    const float2* xv = (const float2*)x;     // row stride 64 float2
#pragma unroll
    for (int r = 0; r < 4; r++) {
        int idx = r * 128 + o;               // 0..511
        int p = idx >> 6, kk = idx & 63;
        int na = n0 + 2 * p, nb = na + 1;
        float2 a = (na < n) ? xv[na * 64 + kk] : make_float2(0.f, 0.f);
        float2 b = (nb < n) ? xv[nb * 64 + kk] : make_float2(0.f, 0.f);
        xsp[p][kk] = make_float4(a.x, b.x, a.y, b.y);
    }
    __syncthreads();
    unsigned long long acc[8];
#pragma unroll
    for (int p = 0; p < 8; p++) acc[p] = 0ull;
    const float2* Wv = (const float2*)W;
#pragma unroll 4
    for (int kk = 0; kk < 64; kk++) {
        float2 w = __ldg(&Wv[o * 64 + kk]);
        unsigned long long wx, wy;
        unsigned wxu = __float_as_uint(w.x), wyu = __float_as_uint(w.y);
        asm("mov.b64 %0, {%1,%1};" : "=l"(wx) : "r"(wxu));
        asm("mov.b64 %0, {%1,%1};" : "=l"(wy) : "r"(wyu));
#pragma unroll
        for (int p = 0; p < 8; p++) {
            ulonglong2 q = *reinterpret_cast<const ulonglong2*>(&xsp[p][kk]);
            asm("fma.rn.f32x2 %0, %1, %2, %0;" : "+l"(acc[p]) : "l"(wx), "l"(q.x));
            asm("fma.rn.f32x2 %0, %1, %2, %0;" : "+l"(acc[p]) : "l"(wy), "l"(q.y));
        }
    }
#pragma unroll
    for (int p = 0; p < 8; p++) {
        unsigned lo, hi;
        asm("mov.b64 {%0,%1}, %2;" : "=r"(lo), "=r"(hi) : "l"(acc[p]));
        int na = n0 + 2 * p;
        if (na < n)     g_h1[na * 128 + o]       = __uint_as_float(lo);
        if (na + 1 < n) g_h1[(na + 1) * 128 + o] = __uint_as_float(hi);
    }
}

// --------- per-node attention scalars, layer 1 (thread per (n,h)) ---------
__global__ void k_att1(const float* __restrict__ att_src, const float* __restrict__ att_dst, int n) {
    int t = blockIdx.x * blockDim.x + threadIdx.x;
    if (t >= n * 8) return;
    int nd = t >> 3, h = t & 7;
    const float4* hv = (const float4*)g_h1 + nd * 32 + h * 4;
    const float4* as = (const float4*)att_src + h * 4;
    const float4* ad = (const float4*)att_dst + h * 4;
    float sa = 0.f, sb = 0.f;
#pragma unroll
    for (int j = 0; j < 4; j++) {
        float4 hq = hv[j], aq = as[j], dq = ad[j];
        sa += hq.x*aq.x + hq.y*aq.y + hq.z*aq.z + hq.w*aq.w;
        sb += hq.x*dq.x + hq.y*dq.y + hq.z*dq.z + hq.w*dq.w;
    }
    g_sA1[t] = sa;   // pairs with dst
    g_sB1[t] = sb;   // pairs with src
}

// ------ layer1 fused gather: softmax-weighted agg + bias + ELU ------------
// one warp per dst node; lane = (head h = lane>>2, 4 channels = float4)
// 4-way edge unroll: 4 independent load chains per iteration (MLP 4x).
__global__ void k_gather1(const float* __restrict__ b1, int n) {
    int w = (blockIdx.x * blockDim.x + threadIdx.x) >> 5;
    if (w >= n) return;
    int lane = threadIdx.x & 31;
    int h = lane >> 2;
    int i   = g_rp[w];
    int end = g_rp[w + 1];
    float sAd = g_sA1[w * 8 + h];
    const float4* h1v = (const float4*)g_h1;
    float4 acc0 = make_float4(0.f,0.f,0.f,0.f);
    float4 acc1 = make_float4(0.f,0.f,0.f,0.f);
    float d0 = 0.f, d1 = 0.f;
    for (; i + 4 <= end; i += 4) {
        int s0 = __ldg(&g_csr[i + 0]);
        int s1 = __ldg(&g_csr[i + 1]);
        int s2 = __ldg(&g_csr[i + 2]);
        int s3 = __ldg(&g_csr[i + 3]);
        float a0 = g_sB1[s0 * 8 + h];
        float a1 = g_sB1[s1 * 8 + h];
        float a2 = g_sB1[s2 * 8 + h];
        float a3 = g_sB1[s3 * 8 + h];
        float4 f0 = h1v[s0 * 32 + lane];
        float4 f1 = h1v[s1 * 32 + lane];
        float4 f2 = h1v[s2 * 32 + lane];
        float4 f3 = h1v[s3 * 32 + lane];
        float e0 = __expf(lrelu(sAd + a0));
        float e1 = __expf(lrelu(sAd + a1));
        float e2 = __expf(lrelu(sAd + a2));
        float e3 = __expf(lrelu(sAd + a3));
        acc0.x = fmaf(e0,f0.x,acc0.x); acc0.y = fmaf(e0,f0.y,acc0.y);
        acc0.z = fmaf(e0,f0.z,acc0.z); acc0.w = fmaf(e0,f0.w,acc0.w);
        acc1.x = fmaf(e1,f1.x,acc1.x); acc1.y = fmaf(e1,f1.y,acc1.y);
        acc1.z = fmaf(e1,f1.z,acc1.z); acc1.w = fmaf(e1,f1.w,acc1.w);
        acc0.x = fmaf(e2,f2.x,acc0.x); acc0.y = fmaf(e2,f2.y,acc0.y);
        acc0.z = fmaf(e2,f2.z,acc0.z); acc0.w = fmaf(e2,f2.w,acc0.w);
        acc1.x = fmaf(e3,f3.x,acc1.x); acc1.y = fmaf(e3,f3.y,acc1.y);
        acc1.z = fmaf(e3,f3.z,acc1.z); acc1.w = fmaf(e3,f3.w,acc1.w);
        d0 += e0 + e2; d1 += e1 + e3;
    }
    for (; i < end; i++) {
        int s = __ldg(&g_csr[i]);
        float e0 = __expf(lrelu(sAd + g_sB1[s * 8 + h]));
        float4 f0 = h1v[s * 32 + lane];
        acc0.x = fmaf(e0,f0.x,acc0.x); acc0.y = fmaf(e0,f0.y,acc0.y);
        acc0.z = fmaf(e0,f0.z,acc0.z); acc0.w = fmaf(e0,f0.w,acc0.w);
        d0 += e0;
    }
    float inv = 1.f / (d0 + d1);
    float4 b = ((const float4*)b1)[lane];
    float4 v;
    v.x = (acc0.x + acc1.x) * inv + b.x;
    v.y = (acc0.y + acc1.y) * inv + b.y;
    v.z = (acc0.z + acc1.z) * inv + b.z;
    v.w = (acc0.w + acc1.w) * inv + b.w;
    v.x = v.x > 0.f ? v.x : (__expf(v.x) - 1.f);
    v.y = v.y > 0.f ? v.y : (__expf(v.y) - 1.f);
    v.z = v.z > 0.f ? v.z : (__expf(v.z) - 1.f);
    v.w = v.w > 0.f ? v.w : (__expf(v.w) - 1.f);
    ((float4*)g_h1e)[w * 32 + lane] = v;
}

// ------------------- GEMM2: h2 = h1e @ W2^T  (N,128)x(128,16) -------------
__global__ void k_gemm2(const float* __restrict__ W2, int n) {
    __shared__ float4 xs[8][32];
    int tid = threadIdx.x;                   // 128 threads
    int n0 = blockIdx.x * 8;
    const float4* hv = (const float4*)g_h1e;
#pragma unroll
    for (int r = 0; r < 2; r++) {
        int idx = r * 128 + tid;
        int i = idx >> 5, k4 = idx & 31;
        int node = n0 + i;
        xs[i][k4] = (node < n) ? hv[node * 32 + k4] : make_float4(0.f, 0.f, 0.f, 0.f);
    }
    __syncthreads();
    int o = tid & 15, i = tid >> 4;
    const float4* Wv = (const float4*)W2;
    float acc = 0.f;
#pragma unroll 4
    for (int k4 = 0; k4 < 32; k4++) {
        float4 w = __ldg(&Wv[o * 32 + k4]);
        float4 xq = xs[i][k4];
        acc = fmaf(w.x, xq.x, fmaf(w.y, xq.y, fmaf(w.z, xq.z, fmaf(w.w, xq.w, acc))));
    }
    int node = n0 + i;
    if (node < n) g_h2[node * 16 + o] = acc;
}

// ------------- per-node attention scalars, layer 2 ------------------------
__global__ void k_att2(const float* __restrict__ att_src, const float* __restrict__ att_dst, int n) {
    int t = blockIdx.x * blockDim.x + threadIdx.x;
    if (t >= n) return;
    const float4* hv = (const float4*)g_h2 + t * 4;
    const float4* as = (const float4*)att_src;
    const float4* ad = (const float4*)att_dst;
    float sa = 0.f, sb = 0.f;
#pragma unroll
    for (int j = 0; j < 4; j++) {
        float4 hq = hv[j], aq = as[j], dq = ad[j];
        sa += hq.x*aq.x + hq.y*aq.y + hq.z*aq.z + hq.w*aq.w;
        sb += hq.x*dq.x + hq.y*dq.y + hq.z*dq.z + hq.w*dq.w;
    }
    g_sA2[t] = sa;
    g_sB2[t] = sb;
}

// ---- layer2 fused gather: softmax agg + bias + log_softmax ---------------
// 16-lane group per dst node (2 dsts per warp); lane = channel; 2-way unroll
__global__ void k_gather2(const float* __restrict__ b2, float* __restrict__ out, int n) {
    int gid = blockIdx.x * blockDim.x + threadIdx.x;
    int g0 = gid >> 4;
    int g = (g0 < n) ? g0 : (n - 1);         // clamp; keep full warp alive for shfl
    int c = gid & 15;
    int i   = g_rp[g];
    int end = g_rp[g + 1];
    float sAd = g_sA2[g];
    float a0 = 0.f, a1 = 0.f, d0 = 0.f, d1 = 0.f;
    for (; i + 2 <= end; i += 2) {
        int s0 = __ldg(&g_csr[i]);
        int s1 = __ldg(&g_csr[i + 1]);
        float b0v = g_sB2[s0], b1v = g_sB2[s1];
        float f0 = g_h2[s0 * 16 + c], f1 = g_h2[s1 * 16 + c];
        float e0 = __expf(lrelu(sAd + b0v));
        float e1 = __expf(lrelu(sAd + b1v));
        a0 = fmaf(e0, f0, a0); d0 += e0;
        a1 = fmaf(e1, f1, a1); d1 += e1;
    }
    if (i < end) {
        int s = __ldg(&g_csr[i]);
        float e0 = __expf(lrelu(sAd + g_sB2[s]));
        a0 = fmaf(e0, g_h2[s * 16 + c], a0); d0 += e0;
    }
    float v = (a0 + a1) / (d0 + d1) + b2[c];
    // log-softmax across the 16 lanes of this dst
    float m = v;
#pragma unroll
    for (int o = 8; o; o >>= 1) m = fmaxf(m, __shfl_xor_sync(0xffffffffu, m, o, 16));
    float ssum = __expf(v - m);
#pragma unroll
    for (int o = 8; o; o >>= 1) ssum += __shfl_xor_sync(0xffffffffu, ssum, o, 16);
    if (g0 < n) out[g0 * 16 + c] = v - m - logf(ssum);
}

// ---------------------------------------------------------------------------
extern "C" void kernel_launch(void* const* d_in, const int* in_sizes, int n_in,
                              void* d_out, int out_size) {
    const float* x   = (const float*)d_in[0];
    const int*   ei  = (const int*)  d_in[1];
    const float* W1  = (const float*)d_in[2];
    const float* as1 = (const float*)d_in[3];
    const float* ad1 = (const float*)d_in[4];
    const float* b1  = (const float*)d_in[5];
    const float* W2  = (const float*)d_in[6];
    const float* as2 = (const float*)d_in[7];
    const float* ad2 = (const float*)d_in[8];
    const float* b2  = (const float*)d_in[9];
    float* out = (float*)d_out;

    int n  = in_sizes[0] / 128;   // 50000 nodes
    int e  = in_sizes[1] / 2;     // 1.6M edges (before self loops)
    int ep = e + n;

    const int BS = 256;
    // CSR build (reused by both layers)
    k_deginit<<<(n + BS - 1) / BS, BS>>>(n);
    k_hist   <<<(e + BS - 1) / BS, BS>>>(ei, e);
    k_scan   <<<1, 1024>>>(n);
    k_scatter<<<(ep + BS - 1) / BS, BS>>>(ei, e, n);
    // layer 1
    k_gemm1  <<<(n + 15) / 16, 128>>>(x, W1, n);
    k_att1   <<<(n * 8 + BS - 1) / BS, BS>>>(as1, ad1, n);
    k_gather1<<<(n * 32 + BS - 1) / BS, BS>>>(b1, n);
    // layer 2
    k_gemm2  <<<(n + 7) / 8, 128>>>(W2, n);
    k_att2   <<<(n + BS - 1) / BS, BS>>>(as2, ad2, n);
    k_gather2<<<(n * 16 + BS - 1) / BS, BS>>>(b2, out, n);
}

// round 7
// speedup vs baseline: 1.0008x; 1.0007x over previous
#include <cuda_runtime.h>
#include <cstdint>

#define MAXN 50000
#define MAXE 1600000

// ---------------- device scratch (no allocations allowed) ----------------
__device__ __align__(16) float g_h1 [MAXN * 128];  // layer1 features  [N,H=8,C=16]
__device__ __align__(16) float g_h1e[MAXN * 128];  // layer1 output after agg+bias+ELU
__device__ __align__(16) float g_sA1[MAXN * 8];    // dot(h1, att_src1) -> used at dst
__device__ __align__(16) float g_sB1[MAXN * 8];    // dot(h1, att_dst1) -> used at src
__device__ __align__(16) float g_h2 [MAXN * 16];   // layer2 features [N,16]
__device__ float g_sA2[MAXN];
__device__ float g_sB2[MAXN];
// CSR by destination (self loops included)
__device__ int g_deg[MAXN];
__device__ int g_rp [MAXN + 1];
__device__ int g_cur[MAXN];
__device__ int g_csr[MAXE + MAXN];

__device__ __forceinline__ float lrelu(float x) { return x > 0.f ? x : 0.2f * x; }

// ------------------------- CSR build --------------------------------------
__global__ void k_deginit(int n) {
    int i = blockIdx.x * blockDim.x + threadIdx.x;
    if (i < n) g_deg[i] = 1;                 // self loop pre-counted
}

__global__ void k_hist(const int* __restrict__ ei, int e) {
    int t = blockIdx.x * blockDim.x + threadIdx.x;
    if (t < e) atomicAdd(&g_deg[ei[e + t]], 1);
}

// single-block exclusive scan of g_deg -> g_rp (and g_cur copy)
__global__ void k_scan(int n) {
    __shared__ int ssum[1024];
    int tid = threadIdx.x;
    int chunk = (n + 1023) >> 10;
    int start = tid * chunk;
    int stop  = min(start + chunk, n);
    int sum = 0;
    for (int i = start; i < stop; i++) sum += g_deg[i];
    ssum[tid] = sum;
    __syncthreads();
    for (int off = 1; off < 1024; off <<= 1) {
        int t = (tid >= off) ? ssum[tid - off] : 0;
        __syncthreads();
        ssum[tid] += t;
        __syncthreads();
    }
    int run = ssum[tid] - sum;               // exclusive prefix
    for (int i = start; i < stop; i++) {
        int d = g_deg[i];
        g_rp[i]  = run;
        g_cur[i] = run;
        run += d;
    }
    if (tid == 1023) g_rp[n] = ssum[1023];
}

__global__ void k_scatter(const int* __restrict__ ei, int e, int n) {
    int t = blockIdx.x * blockDim.x + threadIdx.x;
    int ep = e + n;
    if (t >= ep) return;
    int s, d;
    if (t < e) { s = ei[t]; d = ei[e + t]; } else { s = d = t - e; }
    int pos = atomicAdd(&g_cur[d], 1);
    g_csr[pos] = s;
}

// ------------------- GEMM1: h1 = x @ W1^T  (N,128)x(128,128) --------------
// 128 threads (one per output channel), 16 nodes (8 node-pairs) per block.
// Accumulators are packed f32x2 node-pairs driven by fma.rn.f32x2 (FFMA2):
// halves FMA-pipe work vs scalar FFMA. Smem tile is pair-interleaved so one
// LDS.128 yields two ready-packed 64-bit b-operands (no repack movs).
__global__ void k_gemm1(const float* __restrict__ x, const float* __restrict__ W, int n) {
    __shared__ float4 xsp[8][64];   // [pair][kk]=(x0[2k],x1[2k],x0[2k+1],x1[2k+1])
    int o  = threadIdx.x;
    int n0 = blockIdx.x * 16;
    const float2* xv = (const float2*)x;     // row stride 64 float2
#pragma unroll
    for (int r = 0; r < 4; r++) {
        int idx = r * 128 + o;               // 0..511
        int p = idx >> 6, kk = idx & 63;
        int na = n0 + 2 * p, nb = na + 1;
        float2 a = (na < n) ? xv[na * 64 + kk] : make_float2(0.f, 0.f);
        float2 b = (nb < n) ? xv[nb * 64 + kk] : make_float2(0.f, 0.f);
        xsp[p][kk] = make_float4(a.x, b.x, a.y, b.y);
    }
    __syncthreads();
    unsigned long long acc[8];
#pragma unroll
    for (int p = 0; p < 8; p++) acc[p] = 0ull;
    const float2* Wv = (const float2*)W;
#pragma unroll 4
    for (int kk = 0; kk < 64; kk++) {
        float2 w = __ldg(&Wv[o * 64 + kk]);
        unsigned long long wx, wy;
        unsigned wxu = __float_as_uint(w.x), wyu = __float_as_uint(w.y);
        asm("mov.b64 %0, {%1,%1};" : "=l"(wx) : "r"(wxu));
        asm("mov.b64 %0, {%1,%1};" : "=l"(wy) : "r"(wyu));
#pragma unroll
        for (int p = 0; p < 8; p++) {
            ulonglong2 q = *reinterpret_cast<const ulonglong2*>(&xsp[p][kk]);
            asm("fma.rn.f32x2 %0, %1, %2, %0;" : "+l"(acc[p]) : "l"(wx), "l"(q.x));
            asm("fma.rn.f32x2 %0, %1, %2, %0;" : "+l"(acc[p]) : "l"(wy), "l"(q.y));
        }
    }
#pragma unroll
    for (int p = 0; p < 8; p++) {
        unsigned lo, hi;
        asm("mov.b64 {%0,%1}, %2;" : "=r"(lo), "=r"(hi) : "l"(acc[p]));
        int na = n0 + 2 * p;
        if (na < n)     g_h1[na * 128 + o]       = __uint_as_float(lo);
        if (na + 1 < n) g_h1[(na + 1) * 128 + o] = __uint_as_float(hi);
    }
}

// --------- per-node attention scalars, layer 1 (thread per (n,h)) ---------
__global__ void k_att1(const float* __restrict__ att_src, const float* __restrict__ att_dst, int n) {
    int t = blockIdx.x * blockDim.x + threadIdx.x;
    if (t >= n * 8) return;
    int nd = t >> 3, h = t & 7;
    const float4* hv = (const float4*)g_h1 + nd * 32 + h * 4;
    const float4* as = (const float4*)att_src + h * 4;
    const float4* ad = (const float4*)att_dst + h * 4;
    float sa = 0.f, sb = 0.f;
#pragma unroll
    for (int j = 0; j < 4; j++) {
        float4 hq = hv[j], aq = as[j], dq = ad[j];
        sa += hq.x*aq.x + hq.y*aq.y + hq.z*aq.z + hq.w*aq.w;
        sb += hq.x*dq.x + hq.y*dq.y + hq.z*dq.z + hq.w*dq.w;
    }
    g_sA1[t] = sa;   // pairs with dst
    g_sB1[t] = sb;   // pairs with src
}

// ------ layer1 fused gather: softmax-weighted agg + bias + ELU ------------
// one warp per dst node; lane = (head h = lane>>2, 4 channels = float4)
// 4-way edge unroll: 4 independent load chains per iteration (MLP 4x).
__global__ void k_gather1(const float* __restrict__ b1, int n) {
    int w = (blockIdx.x * blockDim.x + threadIdx.x) >> 5;
    if (w >= n) return;
    int lane = threadIdx.x & 31;
    int h = lane >> 2;
    int i   = g_rp[w];
    int end = g_rp[w + 1];
    float sAd = g_sA1[w * 8 + h];
    const float4* h1v = (const float4*)g_h1;
    float4 acc0 = make_float4(0.f,0.f,0.f,0.f);
    float4 acc1 = make_float4(0.f,0.f,0.f,0.f);
    float d0 = 0.f, d1 = 0.f;
    for (; i + 4 <= end; i += 4) {
        int s0 = __ldg(&g_csr[i + 0]);
        int s1 = __ldg(&g_csr[i + 1]);
        int s2 = __ldg(&g_csr[i + 2]);
        int s3 = __ldg(&g_csr[i + 3]);
        float a0 = g_sB1[s0 * 8 + h];
        float a1 = g_sB1[s1 * 8 + h];
        float a2 = g_sB1[s2 * 8 + h];
        float a3 = g_sB1[s3 * 8 + h];
        float4 f0 = h1v[s0 * 32 + lane];
        float4 f1 = h1v[s1 * 32 + lane];
        float4 f2 = h1v[s2 * 32 + lane];
        float4 f3 = h1v[s3 * 32 + lane];
        float e0 = __expf(lrelu(sAd + a0));
        float e1 = __expf(lrelu(sAd + a1));
        float e2 = __expf(lrelu(sAd + a2));
        float e3 = __expf(lrelu(sAd + a3));
        acc0.x = fmaf(e0,f0.x,acc0.x); acc0.y = fmaf(e0,f0.y,acc0.y);
        acc0.z = fmaf(e0,f0.z,acc0.z); acc0.w = fmaf(e0,f0.w,acc0.w);
        acc1.x = fmaf(e1,f1.x,acc1.x); acc1.y = fmaf(e1,f1.y,acc1.y);
        acc1.z = fmaf(e1,f1.z,acc1.z); acc1.w = fmaf(e1,f1.w,acc1.w);
        acc0.x = fmaf(e2,f2.x,acc0.x); acc0.y = fmaf(e2,f2.y,acc0.y);
        acc0.z = fmaf(e2,f2.z,acc0.z); acc0.w = fmaf(e2,f2.w,acc0.w);
        acc1.x = fmaf(e3,f3.x,acc1.x); acc1.y = fmaf(e3,f3.y,acc1.y);
        acc1.z = fmaf(e3,f3.z,acc1.z); acc1.w = fmaf(e3,f3.w,acc1.w);
        d0 += e0 + e2; d1 += e1 + e3;
    }
    for (; i < end; i++) {
        int s = __ldg(&g_csr[i]);
        float e0 = __expf(lrelu(sAd + g_sB1[s * 8 + h]));
        float4 f0 = h1v[s * 32 + lane];
        acc0.x = fmaf(e0,f0.x,acc0.x); acc0.y = fmaf(e0,f0.y,acc0.y);
        acc0.z = fmaf(e0,f0.z,acc0.z); acc0.w = fmaf(e0,f0.w,acc0.w);
        d0 += e0;
    }
    float inv = 1.f / (d0 + d1);
    float4 b = ((const float4*)b1)[lane];
    float4 v;
    v.x = (acc0.x + acc1.x) * inv + b.x;
    v.y = (acc0.y + acc1.y) * inv + b.y;
    v.z = (acc0.z + acc1.z) * inv + b.z;
    v.w = (acc0.w + acc1.w) * inv + b.w;
    v.x = v.x > 0.f ? v.x : (__expf(v.x) - 1.f);
    v.y = v.y > 0.f ? v.y : (__expf(v.y) - 1.f);
    v.z = v.z > 0.f ? v.z : (__expf(v.z) - 1.f);
    v.w = v.w > 0.f ? v.w : (__expf(v.w) - 1.f);
    ((float4*)g_h1e)[w * 32 + lane] = v;
}

// ------------------- GEMM2: h2 = h1e @ W2^T  (N,128)x(128,16) -------------
__global__ void k_gemm2(const float* __restrict__ W2, int n) {
    __shared__ float4 xs[8][32];
    int tid = threadIdx.x;                   // 128 threads
    int n0 = blockIdx.x * 8;
    const float4* hv = (const float4*)g_h1e;
#pragma unroll
    for (int r = 0; r < 2; r++) {
        int idx = r * 128 + tid;
        int i = idx >> 5, k4 = idx & 31;
        int node = n0 + i;
        xs[i][k4] = (node < n) ? hv[node * 32 + k4] : make_float4(0.f, 0.f, 0.f, 0.f);
    }
    __syncthreads();
    int o = tid & 15, i = tid >> 4;
    const float4* Wv = (const float4*)W2;
    float acc = 0.f;
#pragma unroll 4
    for (int k4 = 0; k4 < 32; k4++) {
        float4 w = __ldg(&Wv[o * 32 + k4]);
        float4 xq = xs[i][k4];
        acc = fmaf(w.x, xq.x, fmaf(w.y, xq.y, fmaf(w.z, xq.z, fmaf(w.w, xq.w, acc))));
    }
    int node = n0 + i;
    if (node < n) g_h2[node * 16 + o] = acc;
}

// ------------- per-node attention scalars, layer 2 ------------------------
__global__ void k_att2(const float* __restrict__ att_src, const float* __restrict__ att_dst, int n) {
    int t = blockIdx.x * blockDim.x + threadIdx.x;
    if (t >= n) return;
    const float4* hv = (const float4*)g_h2 + t * 4;
    const float4* as = (const float4*)att_src;
    const float4* ad = (const float4*)att_dst;
    float sa = 0.f, sb = 0.f;
#pragma unroll
    for (int j = 0; j < 4; j++) {
        float4 hq = hv[j], aq = as[j], dq = ad[j];
        sa += hq.x*aq.x + hq.y*aq.y + hq.z*aq.z + hq.w*aq.w;
        sb += hq.x*dq.x + hq.y*dq.y + hq.z*dq.z + hq.w*dq.w;
    }
    g_sA2[t] = sa;
    g_sB2[t] = sb;
}

// ---- layer2 fused gather: softmax agg + bias + log_softmax ---------------
// 16-lane group per dst node (2 dsts per warp); lane = channel; 2-way unroll
__global__ void k_gather2(const float* __restrict__ b2, float* __restrict__ out, int n) {
    int gid = blockIdx.x * blockDim.x + threadIdx.x;
    int g0 = gid >> 4;
    int g = (g0 < n) ? g0 : (n - 1);         // clamp; keep full warp alive for shfl
    int c = gid & 15;
    int i   = g_rp[g];
    int end = g_rp[g + 1];
    float sAd = g_sA2[g];
    float a0 = 0.f, a1 = 0.f, d0 = 0.f, d1 = 0.f;
    for (; i + 2 <= end; i += 2) {
        int s0 = __ldg(&g_csr[i]);
        int s1 = __ldg(&g_csr[i + 1]);
        float b0v = g_sB2[s0], b1v = g_sB2[s1];
        float f0 = g_h2[s0 * 16 + c], f1 = g_h2[s1 * 16 + c];
        float e0 = __expf(lrelu(sAd + b0v));
        float e1 = __expf(lrelu(sAd + b1v));
        a0 = fmaf(e0, f0, a0); d0 += e0;
        a1 = fmaf(e1, f1, a1); d1 += e1;
    }
    if (i < end) {
        int s = __ldg(&g_csr[i]);
        float e0 = __expf(lrelu(sAd + g_sB2[s]));
        a0 = fmaf(e0, g_h2[s * 16 + c], a0); d0 += e0;
    }
    float v = (a0 + a1) / (d0 + d1) + b2[c];
    // log-softmax across the 16 lanes of this dst
    float m = v;
#pragma unroll
    for (int o = 8; o; o >>= 1) m = fmaxf(m, __shfl_xor_sync(0xffffffffu, m, o, 16));
    float ssum = __expf(v - m);
#pragma unroll
    for (int o = 8; o; o >>= 1) ssum += __shfl_xor_sync(0xffffffffu, ssum, o, 16);
    if (g0 < n) out[g0 * 16 + c] = v - m - logf(ssum);
}

// ---------------------------------------------------------------------------
extern "C" void kernel_launch(void* const* d_in, const int* in_sizes, int n_in,
                              void* d_out, int out_size) {
    const float* x   = (const float*)d_in[0];
    const int*   ei  = (const int*)  d_in[1];
    const float* W1  = (const float*)d_in[2];
    const float* as1 = (const float*)d_in[3];
    const float* ad1 = (const float*)d_in[4];
    const float* b1  = (const float*)d_in[5];
    const float* W2  = (const float*)d_in[6];
    const float* as2 = (const float*)d_in[7];
    const float* ad2 = (const float*)d_in[8];
    const float* b2  = (const float*)d_in[9];
    float* out = (float*)d_out;

    int n  = in_sizes[0] / 128;   // 50000 nodes
    int e  = in_sizes[1] / 2;     // 1.6M edges (before self loops)
    int ep = e + n;

    const int BS = 256;
    // CSR build (reused by both layers)
    k_deginit<<<(n + BS - 1) / BS, BS>>>(n);
    k_hist   <<<(e + BS - 1) / BS, BS>>>(ei, e);
    k_scan   <<<1, 1024>>>(n);
    k_scatter<<<(ep + BS - 1) / BS, BS>>>(ei, e, n);
    // layer 1
    k_gemm1  <<<(n + 15) / 16, 128>>>(x, W1, n);
    k_att1   <<<(n * 8 + BS - 1) / BS, BS>>>(as1, ad1, n);
    k_gather1<<<(n * 32 + BS - 1) / BS, BS>>>(b1, n);
    // layer 2
    k_gemm2  <<<(n + 7) / 8, 128>>>(W2, n);
    k_att2   <<<(n + BS - 1) / BS, BS>>>(as2, ad2, n);
    k_gather2<<<(n * 16 + BS - 1) / BS, BS>>>(b2, out, n);
}